// round 6
// baseline (speedup 1.0000x reference)
#include <cuda_runtime.h>
#include <cuda_fp16.h>
#include <cstdint>
#include <cstddef>

#define NPTS 4096
#define DIM  64
#define NBLK 128     // persistent blocks (<=148 SMs, 1 block/SM -> co-resident)
#define TPB  1024

// ---------------------------------------------------------------------------
// Scratch (allocation-free rule: __device__ globals)
// ---------------------------------------------------------------------------
__device__ float g_sq[NPTS];
__device__ __half g_d2h[(size_t)NPTS * NPTS];        // 32 MB fp16 d^2, L2-resident
__device__ unsigned g_eid[NPTS];                     // winning edge ids (u<<12|v)
__device__ unsigned long long g_best[3][NPTS];       // triple-buffered best keys
__device__ int          g_bar_cnt;
__device__ volatile int g_bar_gen;

static __device__ __forceinline__ float inf32() { return __int_as_float(0x7f800000); }
static __device__ __forceinline__ unsigned long long umin64(unsigned long long a,
                                                            unsigned long long b) {
    return a < b ? a : b;
}
// 64-bit key: (fp16 d^2 bits << 24) | (min(u,v)<<12) | max(u,v)  -- globally
// unique, identical from both endpoints => only mutual 2-cycles possible.
static __device__ __forceinline__ unsigned long long mkkey(unsigned hbits,
                                                           unsigned a, unsigned b) {
    unsigned lo = min(a, b), hi = max(a, b);
    return ((unsigned long long)hbits << 24) | (lo << 12) | hi;
}

static __device__ __forceinline__ void gridbar() {
    __syncthreads();
    if (threadIdx.x == 0) {
        __threadfence();
        int gen = g_bar_gen;
        if (atomicAdd(&g_bar_cnt, 1) == NBLK - 1) {
            g_bar_cnt = 0;
            __threadfence();
            g_bar_gen = gen + 1;
        } else {
            while (g_bar_gen == gen) { }
        }
        __threadfence();
    }
    __syncthreads();
}

// ---------------------------------------------------------------------------
// Kernel 1: warp-per-row squared norms + clear best buffers + barrier reset
// Launch: 128 blocks x 1024 (NPTS warps).
// ---------------------------------------------------------------------------
__global__ void k_init(const float* __restrict__ p) {
    const int t   = threadIdx.x;
    const int gt  = blockIdx.x * TPB + t;
    const int row = gt >> 5;
    const int ln  = gt & 31;

    if (gt == 0) { g_bar_cnt = 0; g_bar_gen = 0; }
    if (gt < 3 * NPTS) ((unsigned long long*)g_best)[gt] = ~0ull;

    float2 v = *(const float2*)(p + (size_t)row * DIM + ln * 2);
    float acc = fmaf(v.x, v.x, v.y * v.y);
#pragma unroll
    for (int s = 16; s > 0; s >>= 1)
        acc += __shfl_down_sync(0xFFFFFFFFu, acc, s);
    if (ln == 0) g_sq[row] = acc;
}

// ---------------------------------------------------------------------------
// Kernel 2: d2 matrix in FP16 (128x128 tile, 8x8/thread, packed f32x2 FMA)
// with fused Boruvka round-0 min-edge epilogue -> atomicMin g_best[0][row].
// ---------------------------------------------------------------------------
__global__ void k_d2(const float* __restrict__ p) {
    __shared__ float As[32][128];
    __shared__ float Bs[32][128];

    const int t  = threadIdx.x;          // 0..255
    const int tx = t & 15;
    const int ty = t >> 4;
    const int i0 = blockIdx.y * 128;
    const int j0 = blockIdx.x * 128;

    const int lr = t >> 1;
    const int lc = (t & 1) * 16;

    unsigned long long acc2[8][4];
#pragma unroll
    for (int m = 0; m < 8; m++)
#pragma unroll
        for (int n = 0; n < 4; n++) acc2[m][n] = 0ull;

#pragma unroll
    for (int k0 = 0; k0 < DIM; k0 += 32) {
#pragma unroll
        for (int q = 0; q < 4; q++) {
            int c = lc + q * 4;
            float4 va = *(const float4*)(p + (size_t)(i0 + lr) * DIM + k0 + c);
            As[c + 0][lr] = va.x; As[c + 1][lr] = va.y;
            As[c + 2][lr] = va.z; As[c + 3][lr] = va.w;
            float4 vb = *(const float4*)(p + (size_t)(j0 + lr) * DIM + k0 + c);
            Bs[c + 0][lr] = vb.x; Bs[c + 1][lr] = vb.y;
            Bs[c + 2][lr] = vb.z; Bs[c + 3][lr] = vb.w;
        }
        __syncthreads();

#pragma unroll
        for (int k = 0; k < 32; k++) {
            uint4 a0 = *(const uint4*)&As[k][ty * 8];
            uint4 a1 = *(const uint4*)&As[k][ty * 8 + 4];
            unsigned au[8] = {a0.x, a0.y, a0.z, a0.w, a1.x, a1.y, a1.z, a1.w};
            ulonglong2 b0 = *(const ulonglong2*)&Bs[k][tx * 8];
            ulonglong2 b1 = *(const ulonglong2*)&Bs[k][tx * 8 + 4];
            unsigned long long bp[4] = {b0.x, b0.y, b1.x, b1.y};
#pragma unroll
            for (int m = 0; m < 8; m++) {
                unsigned long long ap;
                asm("mov.b64 %0, {%1, %1};" : "=l"(ap) : "r"(au[m]));
#pragma unroll
                for (int n = 0; n < 4; n++)
                    asm("fma.rn.f32x2 %0, %1, %2, %0;"
                        : "+l"(acc2[m][n]) : "l"(ap), "l"(bp[n]));
            }
        }
        __syncthreads();
    }

    float sqi[8], sqj[8];
#pragma unroll
    for (int m = 0; m < 8; m++) sqi[m] = g_sq[i0 + ty * 8 + m];
#pragma unroll
    for (int n = 0; n < 8; n++) sqj[n] = g_sq[j0 + tx * 8 + n];

#pragma unroll
    for (int m = 0; m < 8; m++) {
        const int row = i0 + ty * 8 + m;
        unsigned short hb[8];
#pragma unroll
        for (int n = 0; n < 4; n++) {
            unsigned lo, hi;
            asm("mov.b64 {%0, %1}, %2;" : "=r"(lo), "=r"(hi) : "l"(acc2[m][n]));
            float d0 = __uint_as_float(lo), d1 = __uint_as_float(hi);
            float o0 = fmaxf(sqi[m] + sqj[2 * n + 0] - 2.f * d0, 0.f);
            float o1 = fmaxf(sqi[m] + sqj[2 * n + 1] - 2.f * d1, 0.f);
            hb[2 * n + 0] = __half_as_ushort(__float2half_rn(o0));
            hb[2 * n + 1] = __half_as_ushort(__float2half_rn(o1));
        }
        uint4 pack;
        pack.x = (unsigned)hb[0] | ((unsigned)hb[1] << 16);
        pack.y = (unsigned)hb[2] | ((unsigned)hb[3] << 16);
        pack.z = (unsigned)hb[4] | ((unsigned)hb[5] << 16);
        pack.w = (unsigned)hb[6] | ((unsigned)hb[7] << 16);
        *(uint4*)(g_d2h + (size_t)row * NPTS + j0 + tx * 8) = pack;

        // fused round-0 min-edge: row-best as u32 (w16<<16 | col)
        unsigned cand = 0xFFFFFFFFu;
#pragma unroll
        for (int n = 0; n < 8; n++) {
            unsigned jj = (unsigned)(j0 + tx * 8 + n);
            if (jj != (unsigned)row)
                cand = min(cand, ((unsigned)hb[n] << 16) | jj);
        }
#pragma unroll
        for (int s = 8; s > 0; s >>= 1)
            cand = min(cand, __shfl_down_sync(0xFFFFFFFFu, cand, s, 16));
        if (tx == 0) {
            unsigned w = cand >> 16, j = cand & 0xFFFFu;
            atomicMin(&g_best[0][row], mkkey(w, (unsigned)row, j));
        }
    }
}

// ---------------------------------------------------------------------------
// Kernel 3: persistent Boruvka + exact-length recompute + sort.
// One grid barrier per round; all blocks redundantly hook in smem.
// ---------------------------------------------------------------------------
__global__ void __launch_bounds__(TPB, 1) k_mst(const float* __restrict__ p,
                                                float* __restrict__ out) {
    __shared__ unsigned short comp[NPTS];   // 8 KB persistent labels
    __shared__ int par[NPTS];               // 16 KB; reused as float sort buf
    __shared__ int s_m;                     // root (new component) count
    __shared__ int s_cnt;                   // block0 edge counter

    const int t    = threadIdx.x;
    const int wid  = t >> 5;
    const int lane = t & 31;
    const int row  = blockIdx.x * 32 + wid;

    for (int i = t; i < NPTS; i += TPB) comp[i] = (unsigned short)i;
    if (t == 0) s_cnt = 0;
    __syncthreads();

    for (int k = 0; k < 12; k++) {
        if (k > 0) {
            // ---- fp16 min-edge scan, one warp per row, integer compares ----
            const unsigned myc = comp[row];
            const uint4* r4  = (const uint4*)(g_d2h + (size_t)row * NPTS);
            const uint4* c4p = (const uint4*)comp;

            unsigned cand = 0xFFFFFFFFu;
#pragma unroll 4
            for (int s = 0; s < 16; s++) {
                const int q = s * 32 + lane;        // uint4 index (8 halves)
                uint4 dv = r4[q];
                uint4 cv = c4p[q];
                const unsigned cb = (unsigned)(q * 8);
                {   unsigned c0 = cv.x & 0xFFFFu, c1 = cv.x >> 16;
                    if (c0 != myc) cand = min(cand, ((dv.x & 0xFFFFu) << 16) | (cb + 0));
                    if (c1 != myc) cand = min(cand, ((dv.x >> 16) << 16)    | (cb + 1)); }
                {   unsigned c0 = cv.y & 0xFFFFu, c1 = cv.y >> 16;
                    if (c0 != myc) cand = min(cand, ((dv.y & 0xFFFFu) << 16) | (cb + 2));
                    if (c1 != myc) cand = min(cand, ((dv.y >> 16) << 16)    | (cb + 3)); }
                {   unsigned c0 = cv.z & 0xFFFFu, c1 = cv.z >> 16;
                    if (c0 != myc) cand = min(cand, ((dv.z & 0xFFFFu) << 16) | (cb + 4));
                    if (c1 != myc) cand = min(cand, ((dv.z >> 16) << 16)    | (cb + 5)); }
                {   unsigned c0 = cv.w & 0xFFFFu, c1 = cv.w >> 16;
                    if (c0 != myc) cand = min(cand, ((dv.w & 0xFFFFu) << 16) | (cb + 6));
                    if (c1 != myc) cand = min(cand, ((dv.w >> 16) << 16)    | (cb + 7)); }
            }
#pragma unroll
            for (int s = 16; s > 0; s >>= 1)
                cand = min(cand, __shfl_down_sync(0xFFFFFFFFu, cand, s));
            if (lane == 0 && cand != 0xFFFFFFFFu) {
                unsigned w = cand >> 16, j = cand & 0xFFFFu;
                atomicMin(&g_best[k % 3][myc], mkkey(w, (unsigned)row, j));
            }
            gridbar();
        }

        // ---- hook (all blocks, redundant & deterministic) ----
        const unsigned long long* B = g_best[k % 3];
        for (int c = t; c < NPTS; c += TPB) par[c] = c;
        if (t == 0) s_m = 0;
        __syncthreads();

        int local_roots = 0;
        for (int c = t; c < NPTS; c += TPB) {
            unsigned long long key = B[c];
            if (key != ~0ull) {
                unsigned id = (unsigned)(key & 0xFFFFFFull);
                int u = (int)(id >> 12), v = (int)(id & 0xFFF);
                int cu = comp[u], cv = comp[v];
                int other = (cu == c) ? cv : cu;
                bool mutual = (B[other] == key);
                if (!mutual)        par[c] = other;
                else if (c > other) par[c] = other;
                else                local_roots++;
                if (blockIdx.x == 0 && (!mutual || c < other)) {
                    int idx = atomicAdd(&s_cnt, 1);
                    g_eid[idx] = id;
                }
            }
        }
#pragma unroll
        for (int s = 16; s > 0; s >>= 1)
            local_roots += __shfl_down_sync(0xFFFFFFFFu, local_roots, s);
        if (lane == 0 && local_roots) atomicAdd(&s_m, local_roots);
        __syncthreads();

        // pointer jumping with convergence early-exit (race-tolerant,
        // deterministic fixed point = root labels)
        for (int it = 0; it < 12; it++) {
            int chg = 0;
            for (int c = t; c < NPTS; c += TPB) {
                int p1 = par[c];
                int p2 = par[p1];
                if (p2 != p1) { par[c] = p2; chg = 1; }
            }
            if (!__syncthreads_or(chg)) break;
        }

        for (int i = t; i < NPTS; i += TPB)
            comp[i] = (unsigned short)par[comp[i]];
        if (t < 32) g_best[(k + 2) % 3][blockIdx.x * 32 + t] = ~0ull;
        __syncthreads();

        if (s_m <= 1) break;
    }

    if (blockIdx.x != 0) return;

    // ---- exact fp32 lengths for the 4095 winning edges, then bitonic sort --
    __syncthreads();
    float* sh = (float*)par;
    for (int e = t; e < NPTS; e += TPB) {
        if (e < NPTS - 1) {
            unsigned id = g_eid[e];
            int u = (int)(id >> 12), v = (int)(id & 0xFFF);
            const float4* pu = (const float4*)(p + (size_t)u * DIM);
            const float4* pv = (const float4*)(p + (size_t)v * DIM);
            float dot = 0.f;
#pragma unroll
            for (int q = 0; q < DIM / 4; q++) {
                float4 a = pu[q], b = pv[q];
                dot = fmaf(a.x, b.x, dot);
                dot = fmaf(a.y, b.y, dot);
                dot = fmaf(a.z, b.z, dot);
                dot = fmaf(a.w, b.w, dot);
            }
            sh[e] = sqrtf(fmaxf(g_sq[u] + g_sq[v] - 2.f * dot, 0.f));
        } else {
            sh[e] = inf32();
        }
    }
    __syncthreads();

    for (int kk = 2; kk <= NPTS; kk <<= 1) {
        for (int j = kk >> 1; j > 0; j >>= 1) {
#pragma unroll
            for (int tt = 0; tt < 2; tt++) {
                int u = t + tt * TPB;
                int i = ((u & ~(j - 1)) << 1) | (u & (j - 1));
                int l = i | j;
                float a = sh[i], c = sh[l];
                bool up = (i & kk) == 0;
                if ((a > c) == up) { sh[i] = c; sh[l] = a; }
            }
            __syncthreads();
        }
    }
    for (int m = t; m < NPTS - 1; m += TPB) out[m] = sh[m];
}

// ---------------------------------------------------------------------------
extern "C" void kernel_launch(void* const* d_in, const int* in_sizes, int n_in,
                              void* d_out, int out_size) {
    (void)in_sizes; (void)n_in; (void)out_size;
    const float* points = (const float*)d_in[0];
    float* out = (float*)d_out;

    k_init<<<NPTS * 32 / TPB, TPB>>>(points);          // 128 blocks x 1024
    k_d2<<<dim3(NPTS / 128, NPTS / 128), 256>>>(points);
    k_mst<<<NBLK, TPB>>>(points, out);
}